// round 4
// baseline (speedup 1.0000x reference)
#include <cuda_runtime.h>
#include <cuda_bf16.h>

typedef unsigned int u32;
typedef unsigned long long u64;

#define THREADS 512
#define WARPS 16
#define ROWS 32          // 16 warps * 2 rows
#define CTAS 128
#define TSTEPS 64
#define KD 192
#define DT 0.01f

// ---------- shared memory layout (units of 4 bytes) ----------
// Weight pitches multiple of 4 (16B-aligned LDS.128 of 4 k's) and ==4 mod 32:
// for LDS.128 each 8-lane phase covers all 32 banks exactly once -> conflict-free.
#define P_W1 196
#define P_W2 132
#define P_RW2 68
// Activation pitch multiple of 4 (16B-aligned LDS.128 of dup pairs).
#define P_ACT 68

#define OFF_CW1 0
#define OFF_CW2 (OFF_CW1 + 64 * P_W1)
#define OFF_RW1 (OFF_CW2 + 64 * P_W2)
#define OFF_RW2 (OFF_RW1 + 32 * P_W1)
#define OFF_CB1 (OFF_RW2 + 32 * P_RW2)
#define OFF_CB2 (OFF_CB1 + 128)
#define OFF_RB1 (OFF_CB2 + 128)
#define OFF_RB2 (OFF_RB1 + 64)
#define OFF_Y   (OFF_RB2 + 64)
#define OFF_H1  (OFF_Y  + 192 * P_ACT)
#define OFF_R1  (OFF_H1 + 128 * P_ACT)
#define SMEM_FLOATS (OFF_R1 + 64 * P_ACT)
#define SMEM_BYTES (SMEM_FLOATS * 4)   // 223744 bytes <= 227KB opt-in limit

// ---------- packed f32x2 helpers ----------
__device__ __forceinline__ u64 ffma2(u64 a, u64 b, u64 c) {
    u64 d;
    asm("fma.rn.f32x2 %0, %1, %2, %3;" : "=l"(d) : "l"(a), "l"(b), "l"(c));
    return d;
}
// bf16x2 (lo = col 2q, hi = col 2q+1) -> f32x2
__device__ __forceinline__ u64 bf2(u32 v) {
    u32 lo = v << 16;
    u32 hi = v & 0xFFFF0000u;
    u64 r;
    asm("mov.b64 %0, {%1, %2};" : "=l"(r) : "r"(lo), "r"(hi));
    return r;
}
__device__ __forceinline__ u64 pack2(float a, float b) {
    u64 r;
    asm("mov.b64 %0, {%1, %2};" : "=l"(r) : "f"(a), "f"(b));
    return r;
}
__device__ __forceinline__ u64 dup2(float a) { return pack2(a, a); }
__device__ __forceinline__ void unpk(u64 v, float& a, float& b) {
    asm("mov.b64 {%0, %1}, %2;" : "=f"(a), "=f"(b) : "l"(v));
}
__device__ __forceinline__ u32 pkbf(float a, float b) {
    __nv_bfloat162 h = __floats2bfloat162_rn(a, b);  // .x=a (low), .y=b (high)
    return *reinterpret_cast<u32*>(&h);
}
__device__ __forceinline__ float relu(float a) { return fmaxf(a, 0.f); }

__global__ __launch_bounds__(THREADS, 1)
void koopman_kernel(const float* __restrict__ x,
                    const float* __restrict__ cW1, const float* __restrict__ cb1,
                    const float* __restrict__ cW2, const float* __restrict__ cb2,
                    const float* __restrict__ rW1, const float* __restrict__ rb1,
                    const float* __restrict__ rW2, const float* __restrict__ rb2,
                    float* __restrict__ out) {
    extern __shared__ float sm[];
    u32* scw1 = (u32*)(sm + OFF_CW1);
    u32* scw2 = (u32*)(sm + OFF_CW2);
    u32* srw1 = (u32*)(sm + OFF_RW1);
    u32* srw2 = (u32*)(sm + OFF_RW2);
    float* sy  = sm + OFF_Y;
    float* sh1 = sm + OFF_H1;
    float* sr1 = sm + OFF_R1;

    const int tid = threadIdx.x;

    // ---- pack weights to bf16x2 pair-interleaved layout ----
    for (int i = tid; i < 64 * 192; i += THREADS) {
        int q = i / 192, k = i % 192;
        scw1[q * P_W1 + k] = pkbf(cW1[(2 * q) * 192 + k], cW1[(2 * q + 1) * 192 + k]);
    }
    for (int i = tid; i < 64 * 128; i += THREADS) {
        int q = i / 128, k = i % 128;
        scw2[q * P_W2 + k] = pkbf(cW2[(2 * q) * 128 + k], cW2[(2 * q + 1) * 128 + k]);
    }
    for (int i = tid; i < 32 * 192; i += THREADS) {
        int q = i / 192, k = i % 192;
        srw1[q * P_W1 + k] = pkbf(rW1[(2 * q) * 192 + k], rW1[(2 * q + 1) * 192 + k]);
    }
    for (int i = tid; i < 32 * 64; i += THREADS) {
        int q = i / 64, k = i % 64;
        srw2[q * P_RW2 + k] = pkbf(rW2[(2 * q) * 64 + k], rW2[(2 * q + 1) * 64 + k]);
    }
    if (tid < 128) {
        sm[OFF_CB1 + tid] = cb1[tid];
        sm[OFF_CB2 + tid] = cb2[tid];
    }
    if (tid < 64) {
        sm[OFF_RB1 + tid] = rb1[tid];
        sm[OFF_RB2 + tid] = rb2[tid];
    }

    // ---- init duplicated y state from x[:, 0, :] ----
    const int rowBase = blockIdx.x * ROWS;
    for (int i = tid; i < ROWS * KD; i += THREADS) {
        int r = i / KD, c = i % KD;
        float v = x[(size_t)(rowBase + r) * (TSTEPS * KD) + c];
        sy[c * P_ACT + 2 * r]     = v;
        sy[c * P_ACT + 2 * r + 1] = v;
    }
    __syncthreads();

    const int lane = tid & 31;
    const int warp = tid >> 5;
    const int r0   = warp * 2;                // 16 warps * 2 rows = 32 rows
    const float* ysA = sy  + 2 * r0;          // 16B-aligned (16*warp bytes)
    const float* h1A = sh1 + 2 * r0;
    const float* r1A = sr1 + 2 * r0;
    const u32* w1a  = scw1 + lane * P_W1;
    const u32* w1b  = scw1 + (lane + 32) * P_W1;
    const u32* w2a  = scw2 + lane * P_W2;
    const u32* w2b  = scw2 + (lane + 32) * P_W2;
    const u32* rw1a = srw1 + lane * P_W1;
    const u32* rw2a = srw2 + lane * P_RW2;

    const u64 bc1a = pack2(sm[OFF_CB1 + 2 * lane],      sm[OFF_CB1 + 2 * lane + 1]);
    const u64 bc1b = pack2(sm[OFF_CB1 + 2 * lane + 64], sm[OFF_CB1 + 2 * lane + 65]);
    const u64 bc2a = pack2(sm[OFF_CB2 + 2 * lane],      sm[OFF_CB2 + 2 * lane + 1]);
    const u64 bc2b = pack2(sm[OFF_CB2 + 2 * lane + 64], sm[OFF_CB2 + 2 * lane + 65]);
    const u64 br1  = pack2(sm[OFF_RB1 + 2 * lane],      sm[OFF_RB1 + 2 * lane + 1]);
    const u64 br2  = pack2(sm[OFF_RB2 + 2 * lane],      sm[OFF_RB2 + 2 * lane + 1]);

    float* outRow = out + (size_t)rowBase * TSTEPS * KD;

    for (int t = 0; t < TSTEPS; ++t) {
        // ---- Phase A (merged): h1 = relu(y@cW1^T+cb1), r1 = relu(y@rW1^T+rb1) ----
        u64 acc[2][2];
        u64 accr[2];
        acc[0][0] = bc1a; acc[0][1] = bc1b;
        acc[1][0] = bc1a; acc[1][1] = bc1b;
        accr[0] = br1; accr[1] = br1;
#pragma unroll 2
        for (int k = 0; k < 192; k += 4) {
            uint4 WA = *(const uint4*)(w1a + k);
            uint4 WB = *(const uint4*)(w1b + k);
            uint4 WR = *(const uint4*)(rw1a + k);
            u32 wa[4] = {WA.x, WA.y, WA.z, WA.w};
            u32 wb[4] = {WB.x, WB.y, WB.z, WB.w};
            u32 wr[4] = {WR.x, WR.y, WR.z, WR.w};
#pragma unroll
            for (int kk = 0; kk < 4; ++kk) {
                ulonglong2 y = *(const ulonglong2*)(ysA + (k + kk) * P_ACT);
                u64 a = bf2(wa[kk]);
                u64 b = bf2(wb[kk]);
                u64 c = bf2(wr[kk]);
                acc[0][0] = ffma2(y.x, a, acc[0][0]);
                acc[0][1] = ffma2(y.x, b, acc[0][1]);
                accr[0]   = ffma2(y.x, c, accr[0]);
                acc[1][0] = ffma2(y.y, a, acc[1][0]);
                acc[1][1] = ffma2(y.y, b, acc[1][1]);
                accr[1]   = ffma2(y.y, c, accr[1]);
            }
        }
        // ---- A epilogue: relu + duplicated stores (STS.128 of both rows) ----
#pragma unroll
        for (int j = 0; j < 2; ++j) {
            float a0, a1, b0, b1;
            unpk(acc[0][j], a0, b0);
            unpk(acc[1][j], a1, b1);
            int ca = 2 * (lane + 32 * j);
            float* pa = sh1 + ca * P_ACT + 2 * r0;
            float* pb = sh1 + (ca + 1) * P_ACT + 2 * r0;
            *(float4*)(pa) = make_float4(relu(a0), relu(a0), relu(a1), relu(a1));
            *(float4*)(pb) = make_float4(relu(b0), relu(b0), relu(b1), relu(b1));
        }
        {
            float a0, a1, b0, b1;
            unpk(accr[0], a0, b0);
            unpk(accr[1], a1, b1);
            float* pa = sr1 + (2 * lane) * P_ACT + 2 * r0;
            float* pb = sr1 + (2 * lane + 1) * P_ACT + 2 * r0;
            *(float4*)(pa) = make_float4(relu(a0), relu(a0), relu(a1), relu(a1));
            *(float4*)(pb) = make_float4(relu(b0), relu(b0), relu(b1), relu(b1));
        }
        __syncwarp();   // rows are warp-partitioned: A-epi -> B is warp-local

        // ---- Phase B: h = h1 @ cW2^T + cb2 ----
        acc[0][0] = bc2a; acc[0][1] = bc2b;
        acc[1][0] = bc2a; acc[1][1] = bc2b;
#pragma unroll 2
        for (int k = 0; k < 128; k += 4) {
            uint4 WA = *(const uint4*)(w2a + k);
            uint4 WB = *(const uint4*)(w2b + k);
            u32 wa[4] = {WA.x, WA.y, WA.z, WA.w};
            u32 wb[4] = {WB.x, WB.y, WB.z, WB.w};
#pragma unroll
            for (int kk = 0; kk < 4; ++kk) {
                ulonglong2 y = *(const ulonglong2*)(h1A + (k + kk) * P_ACT);
                u64 a = bf2(wa[kk]);
                u64 b = bf2(wb[kk]);
                acc[0][0] = ffma2(y.x, a, acc[0][0]);
                acc[0][1] = ffma2(y.x, b, acc[0][1]);
                acc[1][0] = ffma2(y.y, a, acc[1][0]);
                acc[1][1] = ffma2(y.y, b, acc[1][1]);
            }
        }
        // ---- Phase B: re = r1 @ rW2^T + rb2 ----
        accr[0] = br2; accr[1] = br2;
#pragma unroll 2
        for (int k = 0; k < 64; k += 4) {
            uint4 WR = *(const uint4*)(rw2a + k);
            u32 wr[4] = {WR.x, WR.y, WR.z, WR.w};
#pragma unroll
            for (int kk = 0; kk < 4; ++kk) {
                ulonglong2 y = *(const ulonglong2*)(r1A + (k + kk) * P_ACT);
                u64 c = bf2(wr[kk]);
                accr[0] = ffma2(y.x, c, accr[0]);
                accr[1] = ffma2(y.y, c, accr[1]);
            }
        }

        // ---- Phase C: apply Koopman operator, update y in place, write out ----
#pragma unroll
        for (int j = 0; j < 2; ++j) {
            int q = lane + 32 * j;
#pragma unroll
            for (int rr = 0; rr < 2; ++rr) {
                float mu, om;
                unpk(acc[rr][j], mu, om);
                float e = __expf(DT * mu);
                float s, c;
                __sincosf(DT * om, &s, &c);
                int yi = 2 * (r0 + rr);
                float ye = sy[(2 * q) * P_ACT + yi];
                float yo = sy[(2 * q + 1) * P_ACT + yi];
                float ne = e * (c * ye - s * yo);
                float no = e * (s * ye + c * yo);
                *(u64*)(sy + (2 * q) * P_ACT + yi)     = dup2(ne);
                *(u64*)(sy + (2 * q + 1) * P_ACT + yi) = dup2(no);
                *(float2*)(outRow + (size_t)(r0 + rr) * (TSTEPS * KD) + (size_t)t * KD + 2 * q)
                    = make_float2(ne, no);
            }
        }
#pragma unroll
        for (int rr = 0; rr < 2; ++rr) {
            float ra, rb;
            unpk(accr[rr], ra, rb);
            int c0 = 128 + 2 * lane;
            int yi = 2 * (r0 + rr);
            float ya = sy[c0 * P_ACT + yi];
            float yb = sy[(c0 + 1) * P_ACT + yi];
            float na = ya * __expf(DT * ra);
            float nb = yb * __expf(DT * rb);
            *(u64*)(sy + c0 * P_ACT + yi)       = dup2(na);
            *(u64*)(sy + (c0 + 1) * P_ACT + yi) = dup2(nb);
            *(float2*)(outRow + (size_t)(r0 + rr) * (TSTEPS * KD) + (size_t)t * KD + c0)
                = make_float2(na, nb);
        }
        __syncwarp();   // C -> next A is also warp-local
    }
}

extern "C" void kernel_launch(void* const* d_in, const int* in_sizes, int n_in,
                              void* d_out, int out_size) {
    const float* x   = (const float*)d_in[0];
    const float* cW1 = (const float*)d_in[1];
    const float* cb1 = (const float*)d_in[2];
    const float* cW2 = (const float*)d_in[3];
    const float* cb2 = (const float*)d_in[4];
    const float* rW1 = (const float*)d_in[5];
    const float* rb1 = (const float*)d_in[6];
    const float* rW2 = (const float*)d_in[7];
    const float* rb2 = (const float*)d_in[8];
    float* out = (float*)d_out;

    cudaFuncSetAttribute(koopman_kernel,
                         cudaFuncAttributeMaxDynamicSharedMemorySize, SMEM_BYTES);
    koopman_kernel<<<CTAS, THREADS, SMEM_BYTES>>>(x, cW1, cb1, cW2, cb2,
                                                  rW1, rb1, rW2, rb2, out);
}

// round 5
// speedup vs baseline: 1.1278x; 1.1278x over previous
#include <cuda_runtime.h>
#include <cuda_bf16.h>

typedef unsigned int u32;
typedef unsigned long long u64;

#define THREADS 256
#define ROWS 32          // 8 warps * 4 rows
#define CTAS 128
#define TSTEPS 64
#define KD 192
#define DT 0.01f

// ---------- shared memory layout (units of 4 bytes) ----------
// Weight pitches even (8B-aligned LDS.64 of 2 k's) and ==2 mod 32 (conflict-free).
#define P_W1 194
#define P_W2 130
#define P_RW2 66
// Activation pitch multiple of 4 (16B-aligned LDS.128 of dup pairs).
#define P_ACT 68

#define OFF_CW1 0
#define OFF_CW2 (OFF_CW1 + 64 * P_W1)
#define OFF_RW1 (OFF_CW2 + 64 * P_W2)
#define OFF_RW2 (OFF_RW1 + 32 * P_W1)
#define OFF_CB1 (OFF_RW2 + 32 * P_RW2)
#define OFF_CB2 (OFF_CB1 + 128)
#define OFF_RB1 (OFF_CB2 + 128)
#define OFF_RB2 (OFF_RB1 + 64)
#define OFF_Y   (OFF_RB2 + 64)
#define OFF_H1  (OFF_Y  + 192 * P_ACT)
#define OFF_R1  (OFF_H1 + 128 * P_ACT)
#define SMEM_FLOATS (OFF_R1 + 64 * P_ACT)
#define SMEM_BYTES (SMEM_FLOATS * 4)   // ~222KB <= 227KB opt-in limit

// ---------- packed f32x2 helpers ----------
__device__ __forceinline__ u64 ffma2(u64 a, u64 b, u64 c) {
    u64 d;
    asm("fma.rn.f32x2 %0, %1, %2, %3;" : "=l"(d) : "l"(a), "l"(b), "l"(c));
    return d;
}
__device__ __forceinline__ u64 mul2(u64 a, u64 b) {
    u64 d;
    asm("mul.rn.f32x2 %0, %1, %2;" : "=l"(d) : "l"(a), "l"(b));
    return d;
}
__device__ __forceinline__ u64 add2(u64 a, u64 b) {
    u64 d;
    asm("add.rn.f32x2 %0, %1, %2;" : "=l"(d) : "l"(a), "l"(b));
    return d;
}
// bf16x2 (lo = col 2q, hi = col 2q+1) -> f32x2
__device__ __forceinline__ u64 bf2(u32 v) {
    u32 lo = v << 16;
    u32 hi = v & 0xFFFF0000u;
    u64 r;
    asm("mov.b64 %0, {%1, %2};" : "=l"(r) : "r"(lo), "r"(hi));
    return r;
}
__device__ __forceinline__ u64 pack2(float a, float b) {
    u64 r;
    asm("mov.b64 %0, {%1, %2};" : "=l"(r) : "f"(a), "f"(b));
    return r;
}
__device__ __forceinline__ u64 dup2(float a) { return pack2(a, a); }
__device__ __forceinline__ void unpk(u64 v, float& a, float& b) {
    asm("mov.b64 {%0, %1}, %2;" : "=f"(a), "=f"(b) : "l"(v));
}
__device__ __forceinline__ u32 pkbf(float a, float b) {
    __nv_bfloat162 h = __floats2bfloat162_rn(a, b);  // .x=a (low), .y=b (high)
    return *reinterpret_cast<u32*>(&h);
}
__device__ __forceinline__ float relu(float a) { return fmaxf(a, 0.f); }

__global__ __launch_bounds__(THREADS, 1)
void koopman_kernel(const float* __restrict__ x,
                    const float* __restrict__ cW1, const float* __restrict__ cb1,
                    const float* __restrict__ cW2, const float* __restrict__ cb2,
                    const float* __restrict__ rW1, const float* __restrict__ rb1,
                    const float* __restrict__ rW2, const float* __restrict__ rb2,
                    float* __restrict__ out) {
    extern __shared__ float sm[];
    u32* scw1 = (u32*)(sm + OFF_CW1);
    u32* scw2 = (u32*)(sm + OFF_CW2);
    u32* srw1 = (u32*)(sm + OFF_RW1);
    u32* srw2 = (u32*)(sm + OFF_RW2);
    float* sy  = sm + OFF_Y;
    float* sh1 = sm + OFF_H1;
    float* sr1 = sm + OFF_R1;

    const int tid = threadIdx.x;

    // ---- pack weights to bf16x2 pair-interleaved layout ----
    for (int i = tid; i < 64 * 192; i += THREADS) {
        int q = i / 192, k = i % 192;
        scw1[q * P_W1 + k] = pkbf(cW1[(2 * q) * 192 + k], cW1[(2 * q + 1) * 192 + k]);
    }
    for (int i = tid; i < 64 * 128; i += THREADS) {
        int q = i / 128, k = i % 128;
        scw2[q * P_W2 + k] = pkbf(cW2[(2 * q) * 128 + k], cW2[(2 * q + 1) * 128 + k]);
    }
    for (int i = tid; i < 32 * 192; i += THREADS) {
        int q = i / 192, k = i % 192;
        srw1[q * P_W1 + k] = pkbf(rW1[(2 * q) * 192 + k], rW1[(2 * q + 1) * 192 + k]);
    }
    for (int i = tid; i < 32 * 64; i += THREADS) {
        int q = i / 64, k = i % 64;
        srw2[q * P_RW2 + k] = pkbf(rW2[(2 * q) * 64 + k], rW2[(2 * q + 1) * 64 + k]);
    }
    if (tid < 128) {
        sm[OFF_CB1 + tid] = cb1[tid];
        sm[OFF_CB2 + tid] = cb2[tid];
    }
    if (tid < 64) {
        sm[OFF_RB1 + tid] = rb1[tid];
        sm[OFF_RB2 + tid] = rb2[tid];
    }

    // ---- init duplicated y state from x[:, 0, :] ----
    const int rowBase = blockIdx.x * ROWS;
    for (int i = tid; i < ROWS * KD; i += THREADS) {
        int r = i / KD, c = i % KD;
        float v = x[(size_t)(rowBase + r) * (TSTEPS * KD) + c];
        sy[c * P_ACT + 2 * r]     = v;
        sy[c * P_ACT + 2 * r + 1] = v;
    }
    __syncthreads();

    const int lane = tid & 31;
    const int r0   = (tid >> 5) * 4;          // 8 warps * 4 rows = 32 rows
    const float* ysA = sy  + 2 * r0;
    const float* h1A = sh1 + 2 * r0;
    const float* r1A = sr1 + 2 * r0;
    const u32* w1a  = scw1 + lane * P_W1;
    const u32* w1b  = scw1 + (lane + 32) * P_W1;
    const u32* w2a  = scw2 + lane * P_W2;
    const u32* w2b  = scw2 + (lane + 32) * P_W2;
    const u32* rw1a = srw1 + lane * P_W1;
    const u32* rw2a = srw2 + lane * P_RW2;

    const u64 bc1a = pack2(sm[OFF_CB1 + 2 * lane],      sm[OFF_CB1 + 2 * lane + 1]);
    const u64 bc1b = pack2(sm[OFF_CB1 + 2 * lane + 64], sm[OFF_CB1 + 2 * lane + 65]);
    const u64 bc2a = pack2(sm[OFF_CB2 + 2 * lane],      sm[OFF_CB2 + 2 * lane + 1]);
    const u64 bc2b = pack2(sm[OFF_CB2 + 2 * lane + 64], sm[OFF_CB2 + 2 * lane + 65]);
    const u64 br1  = pack2(sm[OFF_RB1 + 2 * lane],      sm[OFF_RB1 + 2 * lane + 1]);
    const u64 br2  = pack2(sm[OFF_RB2 + 2 * lane],      sm[OFF_RB2 + 2 * lane + 1]);

    // ---- register-resident y state for this thread's (cols, rows) set ----
    // yer[rr] = (y[col 2*lane], y[col 2*(lane+32)])  (even/"ye" components)
    // yor[rr] = (y[col 2*lane+1], y[col 2*(lane+32)+1])
    // yrr[rr] = (y[col 128+2*lane], y[col 129+2*lane])
    u64 yer[4], yor[4], yrr[4];
#pragma unroll
    for (int rr = 0; rr < 4; ++rr) {
        int yi = 2 * (r0 + rr);
        yer[rr] = pack2(sy[(2 * lane) * P_ACT + yi],       sy[(2 * (lane + 32)) * P_ACT + yi]);
        yor[rr] = pack2(sy[(2 * lane + 1) * P_ACT + yi],   sy[(2 * (lane + 32) + 1) * P_ACT + yi]);
        yrr[rr] = pack2(sy[(128 + 2 * lane) * P_ACT + yi], sy[(129 + 2 * lane) * P_ACT + yi]);
    }

    // packed polynomial constants
    const u64 ONE2  = dup2(1.0f);
    const u64 MONE2 = dup2(-1.0f);
    const u64 C05   = dup2(0.5f);
    const u64 C16   = dup2(1.0f / 6.0f);
    const u64 CM05  = dup2(-0.5f);
    const u64 C124  = dup2(1.0f / 24.0f);
    const u64 DT2   = dup2(DT);

    float* outRow = out + (size_t)rowBase * TSTEPS * KD;

    for (int t = 0; t < TSTEPS; ++t) {
        // ---- Phase A (merged): h1 = relu(y@cW1^T+cb1), r1 = relu(y@rW1^T+rb1) ----
        u64 acc[4][2];
        u64 accr[4];
#pragma unroll
        for (int rr = 0; rr < 4; ++rr) { acc[rr][0] = bc1a; acc[rr][1] = bc1b; accr[rr] = br1; }
#pragma unroll 2
        for (int k = 0; k < 192; k += 2) {
            u64 wvA = *(const u64*)(w1a + k);
            u64 wvB = *(const u64*)(w1b + k);
            u64 wvR = *(const u64*)(rw1a + k);
            ulonglong2 y0 = *(const ulonglong2*)(ysA + k * P_ACT);
            ulonglong2 y1 = *(const ulonglong2*)(ysA + k * P_ACT + 4);
            ulonglong2 z0 = *(const ulonglong2*)(ysA + (k + 1) * P_ACT);
            ulonglong2 z1 = *(const ulonglong2*)(ysA + (k + 1) * P_ACT + 4);
            u64 a0 = bf2((u32)wvA), a1 = bf2((u32)(wvA >> 32));
            u64 b0 = bf2((u32)wvB), b1 = bf2((u32)(wvB >> 32));
            u64 c0 = bf2((u32)wvR), c1 = bf2((u32)(wvR >> 32));
            acc[0][0] = ffma2(y0.x, a0, acc[0][0]); acc[0][1] = ffma2(y0.x, b0, acc[0][1]); accr[0] = ffma2(y0.x, c0, accr[0]);
            acc[1][0] = ffma2(y0.y, a0, acc[1][0]); acc[1][1] = ffma2(y0.y, b0, acc[1][1]); accr[1] = ffma2(y0.y, c0, accr[1]);
            acc[2][0] = ffma2(y1.x, a0, acc[2][0]); acc[2][1] = ffma2(y1.x, b0, acc[2][1]); accr[2] = ffma2(y1.x, c0, accr[2]);
            acc[3][0] = ffma2(y1.y, a0, acc[3][0]); acc[3][1] = ffma2(y1.y, b0, acc[3][1]); accr[3] = ffma2(y1.y, c0, accr[3]);
            acc[0][0] = ffma2(z0.x, a1, acc[0][0]); acc[0][1] = ffma2(z0.x, b1, acc[0][1]); accr[0] = ffma2(z0.x, c1, accr[0]);
            acc[1][0] = ffma2(z0.y, a1, acc[1][0]); acc[1][1] = ffma2(z0.y, b1, acc[1][1]); accr[1] = ffma2(z0.y, c1, accr[1]);
            acc[2][0] = ffma2(z1.x, a1, acc[2][0]); acc[2][1] = ffma2(z1.x, b1, acc[2][1]); accr[2] = ffma2(z1.x, c1, accr[2]);
            acc[3][0] = ffma2(z1.y, a1, acc[3][0]); acc[3][1] = ffma2(z1.y, b1, acc[3][1]); accr[3] = ffma2(z1.y, c1, accr[3]);
        }
        // ---- A epilogue: relu + duplicated stores (STS.128 of 2 dup pairs) ----
#pragma unroll
        for (int j = 0; j < 2; ++j) {
            float a0, a1, a2, a3, b0, b1, b2, b3;
            unpk(acc[0][j], a0, b0); unpk(acc[1][j], a1, b1);
            unpk(acc[2][j], a2, b2); unpk(acc[3][j], a3, b3);
            int ca = 2 * (lane + 32 * j);
            float* pa = sh1 + ca * P_ACT + 2 * r0;
            float* pb = sh1 + (ca + 1) * P_ACT + 2 * r0;
            *(float4*)(pa)     = make_float4(relu(a0), relu(a0), relu(a1), relu(a1));
            *(float4*)(pa + 4) = make_float4(relu(a2), relu(a2), relu(a3), relu(a3));
            *(float4*)(pb)     = make_float4(relu(b0), relu(b0), relu(b1), relu(b1));
            *(float4*)(pb + 4) = make_float4(relu(b2), relu(b2), relu(b3), relu(b3));
        }
        {
            float a0, a1, a2, a3, b0, b1, b2, b3;
            unpk(accr[0], a0, b0); unpk(accr[1], a1, b1);
            unpk(accr[2], a2, b2); unpk(accr[3], a3, b3);
            float* pa = sr1 + (2 * lane) * P_ACT + 2 * r0;
            float* pb = sr1 + (2 * lane + 1) * P_ACT + 2 * r0;
            *(float4*)(pa)     = make_float4(relu(a0), relu(a0), relu(a1), relu(a1));
            *(float4*)(pa + 4) = make_float4(relu(a2), relu(a2), relu(a3), relu(a3));
            *(float4*)(pb)     = make_float4(relu(b0), relu(b0), relu(b1), relu(b1));
            *(float4*)(pb + 4) = make_float4(relu(b2), relu(b2), relu(b3), relu(b3));
        }
        __syncwarp();   // rows are warp-partitioned: A-epi -> B is warp-local

        // ---- Phase B: h = h1 @ cW2^T + cb2 ----
#pragma unroll
        for (int rr = 0; rr < 4; ++rr) { acc[rr][0] = bc2a; acc[rr][1] = bc2b; }
#pragma unroll 2
        for (int k = 0; k < 128; k += 2) {
            u64 wvA = *(const u64*)(w2a + k);
            u64 wvB = *(const u64*)(w2b + k);
            ulonglong2 y0 = *(const ulonglong2*)(h1A + k * P_ACT);
            ulonglong2 y1 = *(const ulonglong2*)(h1A + k * P_ACT + 4);
            ulonglong2 z0 = *(const ulonglong2*)(h1A + (k + 1) * P_ACT);
            ulonglong2 z1 = *(const ulonglong2*)(h1A + (k + 1) * P_ACT + 4);
            u64 a0 = bf2((u32)wvA), a1 = bf2((u32)(wvA >> 32));
            u64 b0 = bf2((u32)wvB), b1 = bf2((u32)(wvB >> 32));
            acc[0][0] = ffma2(y0.x, a0, acc[0][0]); acc[0][1] = ffma2(y0.x, b0, acc[0][1]);
            acc[1][0] = ffma2(y0.y, a0, acc[1][0]); acc[1][1] = ffma2(y0.y, b0, acc[1][1]);
            acc[2][0] = ffma2(y1.x, a0, acc[2][0]); acc[2][1] = ffma2(y1.x, b0, acc[2][1]);
            acc[3][0] = ffma2(y1.y, a0, acc[3][0]); acc[3][1] = ffma2(y1.y, b0, acc[3][1]);
            acc[0][0] = ffma2(z0.x, a1, acc[0][0]); acc[0][1] = ffma2(z0.x, b1, acc[0][1]);
            acc[1][0] = ffma2(z0.y, a1, acc[1][0]); acc[1][1] = ffma2(z0.y, b1, acc[1][1]);
            acc[2][0] = ffma2(z1.x, a1, acc[2][0]); acc[2][1] = ffma2(z1.x, b1, acc[2][1]);
            acc[3][0] = ffma2(z1.y, a1, acc[3][0]); acc[3][1] = ffma2(z1.y, b1, acc[3][1]);
        }
        // ---- Phase B: re = r1 @ rW2^T + rb2 ----
#pragma unroll
        for (int rr = 0; rr < 4; ++rr) accr[rr] = br2;
#pragma unroll 2
        for (int k = 0; k < 64; k += 2) {
            u64 wvR = *(const u64*)(rw2a + k);
            ulonglong2 y0 = *(const ulonglong2*)(r1A + k * P_ACT);
            ulonglong2 y1 = *(const ulonglong2*)(r1A + k * P_ACT + 4);
            ulonglong2 z0 = *(const ulonglong2*)(r1A + (k + 1) * P_ACT);
            ulonglong2 z1 = *(const ulonglong2*)(r1A + (k + 1) * P_ACT + 4);
            u64 c0 = bf2((u32)wvR), c1 = bf2((u32)(wvR >> 32));
            accr[0] = ffma2(y0.x, c0, accr[0]);
            accr[1] = ffma2(y0.y, c0, accr[1]);
            accr[2] = ffma2(y1.x, c0, accr[2]);
            accr[3] = ffma2(y1.y, c0, accr[3]);
            accr[0] = ffma2(z0.x, c1, accr[0]);
            accr[1] = ffma2(z0.y, c1, accr[1]);
            accr[2] = ffma2(z1.x, c1, accr[2]);
            accr[3] = ffma2(z1.y, c1, accr[3]);
        }

        // ---- Phase C: packed-polynomial Koopman update, y in registers ----
#pragma unroll
        for (int rr = 0; rr < 4; ++rr) {
            // repack (mu, omega) across the lane's two column-pairs
            float mu0, om0, mu1, om1;
            unpk(acc[rr][0], mu0, om0);
            unpk(acc[rr][1], mu1, om1);
            u64 zmu = mul2(pack2(mu0, mu1), DT2);
            u64 zom = mul2(pack2(om0, om1), DT2);
            // e = 1 + z + z^2*(1/2 + z/6)   (|z| <~ 0.02 -> err ~ z^4/24)
            u64 zmu2 = mul2(zmu, zmu);
            u64 e = ffma2(zmu2, ffma2(zmu, C16, C05), add2(zmu, ONE2));
            // sn = -sin(z) = z*(z^2/6 - 1);  s = -sn;  c = 1 - z^2/2 + z^4/24
            u64 zom2 = mul2(zom, zom);
            u64 sn = mul2(zom, ffma2(zom2, C16, MONE2));
            u64 s  = mul2(sn, MONE2);
            u64 c  = ffma2(zom2, ffma2(zom2, C124, CM05), ONE2);
            u64 ye = yer[rr], yo = yor[rr];
            u64 ne = mul2(e, ffma2(sn, yo, mul2(c, ye)));
            u64 no = mul2(e, ffma2(s,  ye, mul2(c, yo)));
            yer[rr] = ne; yor[rr] = no;
            // reals: yr *= exp(DT*re)
            u64 zr  = mul2(accr[rr], DT2);
            u64 zr2 = mul2(zr, zr);
            u64 er  = ffma2(zr2, ffma2(zr, C16, C05), add2(zr, ONE2));
            u64 yn  = mul2(yrr[rr], er);
            yrr[rr] = yn;

            // stores: SMEM dup copy + GMEM out
            float ne0, ne1, no0, no1, na, nb;
            unpk(ne, ne0, ne1); unpk(no, no0, no1); unpk(yn, na, nb);
            int yi = 2 * (r0 + rr);
            int q0 = 2 * lane, q1 = 2 * (lane + 32), cr = 128 + 2 * lane;
            *(u64*)(sy + q0 * P_ACT + yi)       = dup2(ne0);
            *(u64*)(sy + (q0 + 1) * P_ACT + yi) = dup2(no0);
            *(u64*)(sy + q1 * P_ACT + yi)       = dup2(ne1);
            *(u64*)(sy + (q1 + 1) * P_ACT + yi) = dup2(no1);
            *(u64*)(sy + cr * P_ACT + yi)       = dup2(na);
            *(u64*)(sy + (cr + 1) * P_ACT + yi) = dup2(nb);
            float* orow = outRow + (size_t)(r0 + rr) * (TSTEPS * KD) + (size_t)t * KD;
            *(float2*)(orow + q0) = make_float2(ne0, no0);
            *(float2*)(orow + q1) = make_float2(ne1, no1);
            *(float2*)(orow + cr) = make_float2(na, nb);
        }
        __syncwarp();   // C -> next A is also warp-local
    }
}

extern "C" void kernel_launch(void* const* d_in, const int* in_sizes, int n_in,
                              void* d_out, int out_size) {
    const float* x   = (const float*)d_in[0];
    const float* cW1 = (const float*)d_in[1];
    const float* cb1 = (const float*)d_in[2];
    const float* cW2 = (const float*)d_in[3];
    const float* cb2 = (const float*)d_in[4];
    const float* rW1 = (const float*)d_in[5];
    const float* rb1 = (const float*)d_in[6];
    const float* rW2 = (const float*)d_in[7];
    const float* rb2 = (const float*)d_in[8];
    float* out = (float*)d_out;

    cudaFuncSetAttribute(koopman_kernel,
                         cudaFuncAttributeMaxDynamicSharedMemorySize, SMEM_BYTES);
    koopman_kernel<<<CTAS, THREADS, SMEM_BYTES>>>(x, cW1, cb1, cW2, cb2,
                                                  rW1, rb1, rW2, rb2, out);
}

// round 6
// speedup vs baseline: 1.1353x; 1.0066x over previous
#include <cuda_runtime.h>
#include <cuda_bf16.h>

typedef unsigned int u32;
typedef unsigned long long u64;

#define THREADS 256
#define ROWS 32          // 8 warps * 4 rows
#define CTAS 128
#define TSTEPS 64
#define KD 192
#define DT 0.01f

// ---------- shared memory layout (units of 4 bytes) ----------
#define P_W1 194
#define P_W2 130
#define P_RW2 66
#define P_ACT 68

#define OFF_CW1 0
#define OFF_CW2 (OFF_CW1 + 64 * P_W1)
#define OFF_RW1 (OFF_CW2 + 64 * P_W2)
#define OFF_RW2 (OFF_RW1 + 32 * P_W1)
#define OFF_CB1 (OFF_RW2 + 32 * P_RW2)
#define OFF_CB2 (OFF_CB1 + 128)
#define OFF_RB1 (OFF_CB2 + 128)
#define OFF_RB2 (OFF_RB1 + 64)
#define OFF_Y   (OFF_RB2 + 64)
#define OFF_H1  (OFF_Y  + 192 * P_ACT)
#define OFF_R1  (OFF_H1 + 128 * P_ACT)
#define SMEM_FLOATS (OFF_R1 + 64 * P_ACT)
#define SMEM_BYTES (SMEM_FLOATS * 4)

// ---------- packed f32x2 helpers ----------
__device__ __forceinline__ u64 ffma2(u64 a, u64 b, u64 c) {
    u64 d;
    asm("fma.rn.f32x2 %0, %1, %2, %3;" : "=l"(d) : "l"(a), "l"(b), "l"(c));
    return d;
}
__device__ __forceinline__ u64 mul2(u64 a, u64 b) {
    u64 d;
    asm("mul.rn.f32x2 %0, %1, %2;" : "=l"(d) : "l"(a), "l"(b));
    return d;
}
__device__ __forceinline__ u64 add2(u64 a, u64 b) {
    u64 d;
    asm("add.rn.f32x2 %0, %1, %2;" : "=l"(d) : "l"(a), "l"(b));
    return d;
}
__device__ __forceinline__ u64 bf2(u32 v) {
    u32 lo = v << 16;
    u32 hi = v & 0xFFFF0000u;
    u64 r;
    asm("mov.b64 %0, {%1, %2};" : "=l"(r) : "r"(lo), "r"(hi));
    return r;
}
__device__ __forceinline__ u64 pack2(float a, float b) {
    u64 r;
    asm("mov.b64 %0, {%1, %2};" : "=l"(r) : "f"(a), "f"(b));
    return r;
}
__device__ __forceinline__ u64 dup2(float a) { return pack2(a, a); }
__device__ __forceinline__ void unpk(u64 v, float& a, float& b) {
    asm("mov.b64 {%0, %1}, %2;" : "=f"(a), "=f"(b) : "l"(v));
}
__device__ __forceinline__ u32 pkbf(float a, float b) {
    __nv_bfloat162 h = __floats2bfloat162_rn(a, b);
    return *reinterpret_cast<u32*>(&h);
}
__device__ __forceinline__ float relu(float a) { return fmaxf(a, 0.f); }

// 24-FFMA2 block for merged phase A (consumes wvA/wvB/wvR + y0,y1,z0,z1)
#define A_COMPUTE()                                                                            \
    do {                                                                                       \
        u64 a0 = bf2((u32)wvA), a1 = bf2((u32)(wvA >> 32));                                    \
        u64 b0 = bf2((u32)wvB), b1 = bf2((u32)(wvB >> 32));                                    \
        u64 c0 = bf2((u32)wvR), c1 = bf2((u32)(wvR >> 32));                                    \
        acc[0][0] = ffma2(y0.x, a0, acc[0][0]); acc[0][1] = ffma2(y0.x, b0, acc[0][1]); accr[0] = ffma2(y0.x, c0, accr[0]); \
        acc[1][0] = ffma2(y0.y, a0, acc[1][0]); acc[1][1] = ffma2(y0.y, b0, acc[1][1]); accr[1] = ffma2(y0.y, c0, accr[1]); \
        acc[2][0] = ffma2(y1.x, a0, acc[2][0]); acc[2][1] = ffma2(y1.x, b0, acc[2][1]); accr[2] = ffma2(y1.x, c0, accr[2]); \
        acc[3][0] = ffma2(y1.y, a0, acc[3][0]); acc[3][1] = ffma2(y1.y, b0, acc[3][1]); accr[3] = ffma2(y1.y, c0, accr[3]); \
        acc[0][0] = ffma2(z0.x, a1, acc[0][0]); acc[0][1] = ffma2(z0.x, b1, acc[0][1]); accr[0] = ffma2(z0.x, c1, accr[0]); \
        acc[1][0] = ffma2(z0.y, a1, acc[1][0]); acc[1][1] = ffma2(z0.y, b1, acc[1][1]); accr[1] = ffma2(z0.y, c1, accr[1]); \
        acc[2][0] = ffma2(z1.x, a1, acc[2][0]); acc[2][1] = ffma2(z1.x, b1, acc[2][1]); accr[2] = ffma2(z1.x, c1, accr[2]); \
        acc[3][0] = ffma2(z1.y, a1, acc[3][0]); acc[3][1] = ffma2(z1.y, b1, acc[3][1]); accr[3] = ffma2(z1.y, c1, accr[3]); \
    } while (0)

// 16-FFMA2 block for phase B main GEMM
#define B_COMPUTE()                                                                            \
    do {                                                                                       \
        u64 a0 = bf2((u32)wvA), a1 = bf2((u32)(wvA >> 32));                                    \
        u64 b0 = bf2((u32)wvB), b1 = bf2((u32)(wvB >> 32));                                    \
        acc[0][0] = ffma2(y0.x, a0, acc[0][0]); acc[0][1] = ffma2(y0.x, b0, acc[0][1]);        \
        acc[1][0] = ffma2(y0.y, a0, acc[1][0]); acc[1][1] = ffma2(y0.y, b0, acc[1][1]);        \
        acc[2][0] = ffma2(y1.x, a0, acc[2][0]); acc[2][1] = ffma2(y1.x, b0, acc[2][1]);        \
        acc[3][0] = ffma2(y1.y, a0, acc[3][0]); acc[3][1] = ffma2(y1.y, b0, acc[3][1]);        \
        acc[0][0] = ffma2(z0.x, a1, acc[0][0]); acc[0][1] = ffma2(z0.x, b1, acc[0][1]);        \
        acc[1][0] = ffma2(z0.y, a1, acc[1][0]); acc[1][1] = ffma2(z0.y, b1, acc[1][1]);        \
        acc[2][0] = ffma2(z1.x, a1, acc[2][0]); acc[2][1] = ffma2(z1.x, b1, acc[2][1]);        \
        acc[3][0] = ffma2(z1.y, a1, acc[3][0]); acc[3][1] = ffma2(z1.y, b1, acc[3][1]);        \
    } while (0)

// 8-FFMA2 block for phase B real GEMM
#define R_COMPUTE()                                                                            \
    do {                                                                                       \
        u64 c0 = bf2((u32)wvR), c1 = bf2((u32)(wvR >> 32));                                    \
        accr[0] = ffma2(y0.x, c0, accr[0]);                                                    \
        accr[1] = ffma2(y0.y, c0, accr[1]);                                                    \
        accr[2] = ffma2(y1.x, c0, accr[2]);                                                    \
        accr[3] = ffma2(y1.y, c0, accr[3]);                                                    \
        accr[0] = ffma2(z0.x, c1, accr[0]);                                                    \
        accr[1] = ffma2(z0.y, c1, accr[1]);                                                    \
        accr[2] = ffma2(z1.x, c1, accr[2]);                                                    \
        accr[3] = ffma2(z1.y, c1, accr[3]);                                                    \
    } while (0)

__global__ __launch_bounds__(THREADS, 1)
void koopman_kernel(const float* __restrict__ x,
                    const float* __restrict__ cW1, const float* __restrict__ cb1,
                    const float* __restrict__ cW2, const float* __restrict__ cb2,
                    const float* __restrict__ rW1, const float* __restrict__ rb1,
                    const float* __restrict__ rW2, const float* __restrict__ rb2,
                    float* __restrict__ out) {
    extern __shared__ float sm[];
    u32* scw1 = (u32*)(sm + OFF_CW1);
    u32* scw2 = (u32*)(sm + OFF_CW2);
    u32* srw1 = (u32*)(sm + OFF_RW1);
    u32* srw2 = (u32*)(sm + OFF_RW2);
    float* sy  = sm + OFF_Y;
    float* sh1 = sm + OFF_H1;
    float* sr1 = sm + OFF_R1;

    const int tid = threadIdx.x;

    // ---- pack weights to bf16x2 pair-interleaved layout ----
    for (int i = tid; i < 64 * 192; i += THREADS) {
        int q = i / 192, k = i % 192;
        scw1[q * P_W1 + k] = pkbf(cW1[(2 * q) * 192 + k], cW1[(2 * q + 1) * 192 + k]);
    }
    for (int i = tid; i < 64 * 128; i += THREADS) {
        int q = i / 128, k = i % 128;
        scw2[q * P_W2 + k] = pkbf(cW2[(2 * q) * 128 + k], cW2[(2 * q + 1) * 128 + k]);
    }
    for (int i = tid; i < 32 * 192; i += THREADS) {
        int q = i / 192, k = i % 192;
        srw1[q * P_W1 + k] = pkbf(rW1[(2 * q) * 192 + k], rW1[(2 * q + 1) * 192 + k]);
    }
    for (int i = tid; i < 32 * 64; i += THREADS) {
        int q = i / 64, k = i % 64;
        srw2[q * P_RW2 + k] = pkbf(rW2[(2 * q) * 64 + k], rW2[(2 * q + 1) * 64 + k]);
    }
    if (tid < 128) {
        sm[OFF_CB1 + tid] = cb1[tid];
        sm[OFF_CB2 + tid] = cb2[tid];
    }
    if (tid < 64) {
        sm[OFF_RB1 + tid] = rb1[tid];
        sm[OFF_RB2 + tid] = rb2[tid];
    }

    // ---- init duplicated y state from x[:, 0, :] ----
    const int rowBase = blockIdx.x * ROWS;
    for (int i = tid; i < ROWS * KD; i += THREADS) {
        int r = i / KD, c = i % KD;
        float v = x[(size_t)(rowBase + r) * (TSTEPS * KD) + c];
        sy[c * P_ACT + 2 * r]     = v;
        sy[c * P_ACT + 2 * r + 1] = v;
    }
    __syncthreads();

    const int lane = tid & 31;
    const int r0   = (tid >> 5) * 4;
    const float* ysA = sy  + 2 * r0;
    const float* h1A = sh1 + 2 * r0;
    const float* r1A = sr1 + 2 * r0;
    const u32* w1a  = scw1 + lane * P_W1;
    const u32* w1b  = scw1 + (lane + 32) * P_W1;
    const u32* w2a  = scw2 + lane * P_W2;
    const u32* w2b  = scw2 + (lane + 32) * P_W2;
    const u32* rw1a = srw1 + lane * P_W1;
    const u32* rw2a = srw2 + lane * P_RW2;

    const u64 bc1a = pack2(sm[OFF_CB1 + 2 * lane],      sm[OFF_CB1 + 2 * lane + 1]);
    const u64 bc1b = pack2(sm[OFF_CB1 + 2 * lane + 64], sm[OFF_CB1 + 2 * lane + 65]);
    const u64 bc2a = pack2(sm[OFF_CB2 + 2 * lane],      sm[OFF_CB2 + 2 * lane + 1]);
    const u64 bc2b = pack2(sm[OFF_CB2 + 2 * lane + 64], sm[OFF_CB2 + 2 * lane + 65]);
    const u64 br1  = pack2(sm[OFF_RB1 + 2 * lane],      sm[OFF_RB1 + 2 * lane + 1]);
    const u64 br2  = pack2(sm[OFF_RB2 + 2 * lane],      sm[OFF_RB2 + 2 * lane + 1]);

    // register-resident y state
    u64 yer[4], yor[4], yrr[4];
#pragma unroll
    for (int rr = 0; rr < 4; ++rr) {
        int yi = 2 * (r0 + rr);
        yer[rr] = pack2(sy[(2 * lane) * P_ACT + yi],       sy[(2 * (lane + 32)) * P_ACT + yi]);
        yor[rr] = pack2(sy[(2 * lane + 1) * P_ACT + yi],   sy[(2 * (lane + 32) + 1) * P_ACT + yi]);
        yrr[rr] = pack2(sy[(128 + 2 * lane) * P_ACT + yi], sy[(129 + 2 * lane) * P_ACT + yi]);
    }

    const u64 ONE2  = dup2(1.0f);
    const u64 MONE2 = dup2(-1.0f);
    const u64 C05   = dup2(0.5f);
    const u64 C16   = dup2(1.0f / 6.0f);
    const u64 CM05  = dup2(-0.5f);
    const u64 C124  = dup2(1.0f / 24.0f);
    const u64 DT2   = dup2(DT);

    float* outRow = out + (size_t)rowBase * TSTEPS * KD;

    for (int t = 0; t < TSTEPS; ++t) {
        // ================= Phase A (software-pipelined) =================
        u64 acc[4][2];
        u64 accr[4];
#pragma unroll
        for (int rr = 0; rr < 4; ++rr) { acc[rr][0] = bc1a; acc[rr][1] = bc1b; accr[rr] = br1; }
        // prefetch k=0/1
        u64 pwA = *(const u64*)(w1a);
        u64 pwB = *(const u64*)(w1b);
        u64 pwR = *(const u64*)(rw1a);
        ulonglong2 py0 = *(const ulonglong2*)(ysA);
        ulonglong2 py1 = *(const ulonglong2*)(ysA + 4);
        ulonglong2 pz0 = *(const ulonglong2*)(ysA + P_ACT);
        ulonglong2 pz1 = *(const ulonglong2*)(ysA + P_ACT + 4);
#pragma unroll 2
        for (int k = 0; k < 190; k += 2) {
            u64 wvA = pwA, wvB = pwB, wvR = pwR;
            ulonglong2 y0 = py0, y1 = py1, z0 = pz0, z1 = pz1;
            // prefetch k+2/k+3
            pwA = *(const u64*)(w1a + k + 2);
            pwB = *(const u64*)(w1b + k + 2);
            pwR = *(const u64*)(rw1a + k + 2);
            py0 = *(const ulonglong2*)(ysA + (k + 2) * P_ACT);
            py1 = *(const ulonglong2*)(ysA + (k + 2) * P_ACT + 4);
            pz0 = *(const ulonglong2*)(ysA + (k + 3) * P_ACT);
            pz1 = *(const ulonglong2*)(ysA + (k + 3) * P_ACT + 4);
            A_COMPUTE();
        }
        {   // tail k=190/191
            u64 wvA = pwA, wvB = pwB, wvR = pwR;
            ulonglong2 y0 = py0, y1 = py1, z0 = pz0, z1 = pz1;
            A_COMPUTE();
        }
        // ---- A epilogue: relu + duplicated stores ----
#pragma unroll
        for (int j = 0; j < 2; ++j) {
            float a0, a1, a2, a3, b0, b1, b2, b3;
            unpk(acc[0][j], a0, b0); unpk(acc[1][j], a1, b1);
            unpk(acc[2][j], a2, b2); unpk(acc[3][j], a3, b3);
            int ca = 2 * (lane + 32 * j);
            float* pa = sh1 + ca * P_ACT + 2 * r0;
            float* pb = sh1 + (ca + 1) * P_ACT + 2 * r0;
            *(float4*)(pa)     = make_float4(relu(a0), relu(a0), relu(a1), relu(a1));
            *(float4*)(pa + 4) = make_float4(relu(a2), relu(a2), relu(a3), relu(a3));
            *(float4*)(pb)     = make_float4(relu(b0), relu(b0), relu(b1), relu(b1));
            *(float4*)(pb + 4) = make_float4(relu(b2), relu(b2), relu(b3), relu(b3));
        }
        {
            float a0, a1, a2, a3, b0, b1, b2, b3;
            unpk(accr[0], a0, b0); unpk(accr[1], a1, b1);
            unpk(accr[2], a2, b2); unpk(accr[3], a3, b3);
            float* pa = sr1 + (2 * lane) * P_ACT + 2 * r0;
            float* pb = sr1 + (2 * lane + 1) * P_ACT + 2 * r0;
            *(float4*)(pa)     = make_float4(relu(a0), relu(a0), relu(a1), relu(a1));
            *(float4*)(pa + 4) = make_float4(relu(a2), relu(a2), relu(a3), relu(a3));
            *(float4*)(pb)     = make_float4(relu(b0), relu(b0), relu(b1), relu(b1));
            *(float4*)(pb + 4) = make_float4(relu(b2), relu(b2), relu(b3), relu(b3));
        }
        __syncwarp();

        // ================= Phase B main (software-pipelined) =================
#pragma unroll
        for (int rr = 0; rr < 4; ++rr) { acc[rr][0] = bc2a; acc[rr][1] = bc2b; }
        pwA = *(const u64*)(w2a);
        pwB = *(const u64*)(w2b);
        py0 = *(const ulonglong2*)(h1A);
        py1 = *(const ulonglong2*)(h1A + 4);
        pz0 = *(const ulonglong2*)(h1A + P_ACT);
        pz1 = *(const ulonglong2*)(h1A + P_ACT + 4);
#pragma unroll 2
        for (int k = 0; k < 126; k += 2) {
            u64 wvA = pwA, wvB = pwB;
            ulonglong2 y0 = py0, y1 = py1, z0 = pz0, z1 = pz1;
            pwA = *(const u64*)(w2a + k + 2);
            pwB = *(const u64*)(w2b + k + 2);
            py0 = *(const ulonglong2*)(h1A + (k + 2) * P_ACT);
            py1 = *(const ulonglong2*)(h1A + (k + 2) * P_ACT + 4);
            pz0 = *(const ulonglong2*)(h1A + (k + 3) * P_ACT);
            pz1 = *(const ulonglong2*)(h1A + (k + 3) * P_ACT + 4);
            B_COMPUTE();
        }
        {   // tail k=126/127
            u64 wvA = pwA, wvB = pwB;
            ulonglong2 y0 = py0, y1 = py1, z0 = pz0, z1 = pz1;
            B_COMPUTE();
        }

        // ================= Phase B real (software-pipelined) =================
#pragma unroll
        for (int rr = 0; rr < 4; ++rr) accr[rr] = br2;
        u64 pwRr = *(const u64*)(rw2a);
        py0 = *(const ulonglong2*)(r1A);
        py1 = *(const ulonglong2*)(r1A + 4);
        pz0 = *(const ulonglong2*)(r1A + P_ACT);
        pz1 = *(const ulonglong2*)(r1A + P_ACT + 4);
#pragma unroll 2
        for (int k = 0; k < 62; k += 2) {
            u64 wvR = pwRr;
            ulonglong2 y0 = py0, y1 = py1, z0 = pz0, z1 = pz1;
            pwRr = *(const u64*)(rw2a + k + 2);
            py0 = *(const ulonglong2*)(r1A + (k + 2) * P_ACT);
            py1 = *(const ulonglong2*)(r1A + (k + 2) * P_ACT + 4);
            pz0 = *(const ulonglong2*)(r1A + (k + 3) * P_ACT);
            pz1 = *(const ulonglong2*)(r1A + (k + 3) * P_ACT + 4);
            R_COMPUTE();
        }
        {   // tail k=62/63
            u64 wvR = pwRr;
            ulonglong2 y0 = py0, y1 = py1, z0 = pz0, z1 = pz1;
            R_COMPUTE();
        }

        // ================= Phase C: packed-polynomial update =================
#pragma unroll
        for (int rr = 0; rr < 4; ++rr) {
            float mu0, om0, mu1, om1;
            unpk(acc[rr][0], mu0, om0);
            unpk(acc[rr][1], mu1, om1);
            u64 zmu = mul2(pack2(mu0, mu1), DT2);
            u64 zom = mul2(pack2(om0, om1), DT2);
            u64 zmu2 = mul2(zmu, zmu);
            u64 e = ffma2(zmu2, ffma2(zmu, C16, C05), add2(zmu, ONE2));
            u64 zom2 = mul2(zom, zom);
            u64 sn = mul2(zom, ffma2(zom2, C16, MONE2));
            u64 s  = mul2(sn, MONE2);
            u64 c  = ffma2(zom2, ffma2(zom2, C124, CM05), ONE2);
            u64 ye = yer[rr], yo = yor[rr];
            u64 ne = mul2(e, ffma2(sn, yo, mul2(c, ye)));
            u64 no = mul2(e, ffma2(s,  ye, mul2(c, yo)));
            yer[rr] = ne; yor[rr] = no;
            u64 zr  = mul2(accr[rr], DT2);
            u64 zr2 = mul2(zr, zr);
            u64 er  = ffma2(zr2, ffma2(zr, C16, C05), add2(zr, ONE2));
            u64 yn  = mul2(yrr[rr], er);
            yrr[rr] = yn;

            float ne0, ne1, no0, no1, na, nb;
            unpk(ne, ne0, ne1); unpk(no, no0, no1); unpk(yn, na, nb);
            int yi = 2 * (r0 + rr);
            int q0 = 2 * lane, q1 = 2 * (lane + 32), cr = 128 + 2 * lane;
            *(u64*)(sy + q0 * P_ACT + yi)       = dup2(ne0);
            *(u64*)(sy + (q0 + 1) * P_ACT + yi) = dup2(no0);
            *(u64*)(sy + q1 * P_ACT + yi)       = dup2(ne1);
            *(u64*)(sy + (q1 + 1) * P_ACT + yi) = dup2(no1);
            *(u64*)(sy + cr * P_ACT + yi)       = dup2(na);
            *(u64*)(sy + (cr + 1) * P_ACT + yi) = dup2(nb);
            float* orow = outRow + (size_t)(r0 + rr) * (TSTEPS * KD) + (size_t)t * KD;
            *(float2*)(orow + q0) = make_float2(ne0, no0);
            *(float2*)(orow + q1) = make_float2(ne1, no1);
            *(float2*)(orow + cr) = make_float2(na, nb);
        }
        __syncwarp();
    }
}

extern "C" void kernel_launch(void* const* d_in, const int* in_sizes, int n_in,
                              void* d_out, int out_size) {
    const float* x   = (const float*)d_in[0];
    const float* cW1 = (const float*)d_in[1];
    const float* cb1 = (const float*)d_in[2];
    const float* cW2 = (const float*)d_in[3];
    const float* cb2 = (const float*)d_in[4];
    const float* rW1 = (const float*)d_in[5];
    const float* rb1 = (const float*)d_in[6];
    const float* rW2 = (const float*)d_in[7];
    const float* rb2 = (const float*)d_in[8];
    float* out = (float*)d_out;

    cudaFuncSetAttribute(koopman_kernel,
                         cudaFuncAttributeMaxDynamicSharedMemorySize, SMEM_BYTES);
    koopman_kernel<<<CTAS, THREADS, SMEM_BYTES>>>(x, cW1, cb1, cW2, cb2,
                                                  rW1, rb1, rW2, rb2, out);
}

// round 9
// speedup vs baseline: 5.0587x; 4.4559x over previous
#include <cuda_runtime.h>
#include <cuda_bf16.h>

typedef unsigned int u32;
typedef unsigned long long u64;

#define THREADS 256
#define CTAS 128
#define ROWS 32
#define TSTEPS 64
#define KD 192
#define DT 0.01f

#define WPAD1 200   // halves per row for yA / h1 / WB1  (400 B ≡ 16 mod 128 -> ldmatrix conflict-free)
#define WPAD2 136   // halves per row for WB2            (272 B ≡ 16 mod 128)

// ---- smem byte offsets ----
#define SB_YA  0                          // [32][200] bf16 = 12800 B
#define SB_H1  12800                      // [32][200] bf16 = 12800 B
#define SB_WB1 25600                      // [192][200] bf16 = 76800 B (merged cW1 / rW1, n-major)
#define SB_WB2 102400                     // [192][136] bf16 = 52224 B (merged cW2 / rW2)
#define SB_B1  154624                     // [192] f32 merged bias1
#define SB_B2  155392                     // [192] f32 merged bias2
#define SMEM_BYTES 156160

__device__ __forceinline__ u32 smem_u32(const void* p) {
    u32 a;
    asm("{ .reg .u64 t; cvta.to.shared.u64 t, %1; cvt.u32.u64 %0, t; }" : "=r"(a) : "l"(p));
    return a;
}
__device__ __forceinline__ void ldsm4(u32* r, u32 addr) {
    asm volatile("ldmatrix.sync.aligned.m8n8.x4.shared.b16 {%0,%1,%2,%3}, [%4];"
                 : "=r"(r[0]), "=r"(r[1]), "=r"(r[2]), "=r"(r[3]) : "r"(addr));
}
__device__ __forceinline__ void ldsm2(u32* r, u32 addr) {
    asm volatile("ldmatrix.sync.aligned.m8n8.x2.shared.b16 {%0,%1}, [%2];"
                 : "=r"(r[0]), "=r"(r[1]) : "r"(addr));
}
__device__ __forceinline__ void mma16816(float* d, const u32* a, const u32* b) {
    asm volatile(
        "mma.sync.aligned.m16n8k16.row.col.f32.bf16.bf16.f32 "
        "{%0,%1,%2,%3}, {%4,%5,%6,%7}, {%8,%9}, {%0,%1,%2,%3};"
        : "+f"(d[0]), "+f"(d[1]), "+f"(d[2]), "+f"(d[3])
        : "r"(a[0]), "r"(a[1]), "r"(a[2]), "r"(a[3]), "r"(b[0]), "r"(b[1]));
}
__device__ __forceinline__ u32 pkbf(float a, float b) {
    __nv_bfloat162 h = __floats2bfloat162_rn(a, b);
    return *reinterpret_cast<u32*>(&h);
}
__device__ __forceinline__ float relu(float a) { return fmaxf(a, 0.f); }

__global__ __launch_bounds__(THREADS, 1)
void koopman_mma_kernel(const float* __restrict__ x,
                        const float* __restrict__ cW1, const float* __restrict__ cb1,
                        const float* __restrict__ cW2, const float* __restrict__ cb2,
                        const float* __restrict__ rW1, const float* __restrict__ rb1,
                        const float* __restrict__ rW2, const float* __restrict__ rb2,
                        float* __restrict__ out) {
    extern __shared__ char smem[];
    const u32 sbase = smem_u32(smem);
    const int tid = threadIdx.x;
    const int wid = tid >> 5;
    const int lane = tid & 31;

    __nv_bfloat16* WB1 = (__nv_bfloat16*)(smem + SB_WB1);
    __nv_bfloat16* WB2 = (__nv_bfloat16*)(smem + SB_WB2);
    float* sB1 = (float*)(smem + SB_B1);
    float* sB2 = (float*)(smem + SB_B2);
    u32* h1w = (u32*)(smem + SB_H1);
    u32* yAw = (u32*)(smem + SB_YA);

    // ---- pack merged weights (fp32 -> bf16) ----
    for (int i = tid; i < 192 * 192; i += THREADS) {
        int n = i / 192, k = i % 192;
        float v = (n < 128) ? cW1[n * 192 + k] : rW1[(n - 128) * 192 + k];
        WB1[n * WPAD1 + k] = __float2bfloat16(v);
    }
    for (int i = tid; i < 192 * 128; i += THREADS) {
        int n = i / 128, k = i % 128;
        if (n < 128)      WB2[n * WPAD2 + k] = __float2bfloat16(cW2[n * 128 + k]);
        else if (k < 64)  WB2[n * WPAD2 + k] = __float2bfloat16(rW2[(n - 128) * 64 + k]);
    }
    if (tid < 192) {
        sB1[tid] = (tid < 128) ? cb1[tid] : rb1[tid - 128];
        sB2[tid] = (tid < 128) ? cb2[tid] : rb2[tid - 128];
    }

    // ---- fragment geometry ----
    const int g = lane >> 3;
    const int rowA = ((g & 1) << 3) + (lane & 7);   // 0..15
    const int colA = (g >> 1) << 3;                 // 0 or 8
    const int rowB = lane & 7;
    const int colB = (g & 1) << 3;

    // warp n-tiles: w, w+8, w+16 -> cols 8w, 64+8w, 128+8w (2 complex + 1 real tile)
    int n0[3] = {8 * wid, 64 + 8 * wid, 128 + 8 * wid};

    const int rowBase = blockIdx.x * ROWS;
    const int fr = lane >> 2;                       // fragment row 0..7
    const int fc = 2 * (lane & 3);                  // fragment col offset (even)

    // ---- register y-state matching D-fragment layout ----
    // y[mt*3+i][0,1] = y[mt*16+fr][n0[i]+fc, +1] ; [2,3] = row +8
    float y[6][4];
#pragma unroll
    for (int mt = 0; mt < 2; ++mt)
#pragma unroll
        for (int i = 0; i < 3; ++i) {
            int p = n0[i] + fc;
            const float* xr = x + (size_t)(rowBase + mt * 16 + fr) * (TSTEPS * KD) + p;
            float2 v0 = *(const float2*)(xr);
            float2 v1 = *(const float2*)(xr + 8 * (TSTEPS * KD));
            y[mt * 3 + i][0] = v0.x; y[mt * 3 + i][1] = v0.y;
            y[mt * 3 + i][2] = v1.x; y[mt * 3 + i][3] = v1.y;
        }
    // initial yA (bf16 A operand)
#pragma unroll
    for (int mt = 0; mt < 2; ++mt)
#pragma unroll
        for (int i = 0; i < 3; ++i) {
            int p = n0[i] + fc;
            int r0w = mt * 16 + fr;
            yAw[(r0w * WPAD1 + p) >> 1]       = pkbf(y[mt * 3 + i][0], y[mt * 3 + i][1]);
            yAw[((r0w + 8) * WPAD1 + p) >> 1] = pkbf(y[mt * 3 + i][2], y[mt * 3 + i][3]);
        }
    __syncthreads();

    const u32 yAb  = sbase + SB_YA;
    const u32 h1b  = sbase + SB_H1;
    const u32 wb1b = sbase + SB_WB1;
    const u32 wb2b = sbase + SB_WB2;

    float* outBase = out + (size_t)rowBase * TSTEPS * KD;

    for (int t = 0; t < TSTEPS; ++t) {
        // ===== GEMM1: [32,192] = yA[32,192] @ WB1^T, K=192 =====
        float d[6][4];
#pragma unroll
        for (int j = 0; j < 6; ++j) { d[j][0] = d[j][1] = d[j][2] = d[j][3] = 0.f; }
#pragma unroll
        for (int kt = 0; kt < 12; ++kt) {
            u32 a0[4], a1[4];
            ldsm4(a0, yAb + (u32)((rowA) * WPAD1 + kt * 16 + colA) * 2);
            ldsm4(a1, yAb + (u32)((16 + rowA) * WPAD1 + kt * 16 + colA) * 2);
#pragma unroll
            for (int i = 0; i < 3; ++i) {
                u32 b[2];
                ldsm2(b, wb1b + (u32)((n0[i] + rowB) * WPAD1 + kt * 16 + colB) * 2);
                mma16816(d[i], a0, b);
                mma16816(d[3 + i], a1, b);
            }
        }
        // epilogue 1: bias + relu -> h1 (bf16)
#pragma unroll
        for (int mt = 0; mt < 2; ++mt)
#pragma unroll
            for (int i = 0; i < 3; ++i) {
                int p = n0[i] + fc;
                float2 bb = *(const float2*)(sB1 + p);
                int r0w = mt * 16 + fr;
                float* dd = d[mt * 3 + i];
                h1w[(r0w * WPAD1 + p) >> 1]       = pkbf(relu(dd[0] + bb.x), relu(dd[1] + bb.y));
                h1w[((r0w + 8) * WPAD1 + p) >> 1] = pkbf(relu(dd[2] + bb.x), relu(dd[3] + bb.y));
            }
        __syncthreads();

        // ===== GEMM2: complex tiles (K=128 from h1[:,0:128]), real tile (K=64 from h1[:,128:192]) =====
        float e[6][4];
#pragma unroll
        for (int j = 0; j < 6; ++j) { e[j][0] = e[j][1] = e[j][2] = e[j][3] = 0.f; }
#pragma unroll
        for (int kt = 0; kt < 8; ++kt) {
            u32 a0[4], a1[4];
            ldsm4(a0, h1b + (u32)((rowA) * WPAD1 + kt * 16 + colA) * 2);
            ldsm4(a1, h1b + (u32)((16 + rowA) * WPAD1 + kt * 16 + colA) * 2);
#pragma unroll
            for (int i = 0; i < 2; ++i) {
                u32 b[2];
                ldsm2(b, wb2b + (u32)((n0[i] + rowB) * WPAD2 + kt * 16 + colB) * 2);
                mma16816(e[i], a0, b);
                mma16816(e[3 + i], a1, b);
            }
        }
#pragma unroll
        for (int kt = 0; kt < 4; ++kt) {
            u32 a0[4], a1[4];
            ldsm4(a0, h1b + (u32)((rowA) * WPAD1 + 128 + kt * 16 + colA) * 2);
            ldsm4(a1, h1b + (u32)((16 + rowA) * WPAD1 + 128 + kt * 16 + colA) * 2);
            u32 b[2];
            ldsm2(b, wb2b + (u32)((n0[2] + rowB) * WPAD2 + kt * 16 + colB) * 2);
            mma16816(e[2], a0, b);
            mma16816(e[5], a1, b);
        }

        // ===== Phase C: Koopman update (polynomial exp/sin/cos), y fp32 in regs =====
#pragma unroll
        for (int mt = 0; mt < 2; ++mt) {
#pragma unroll
            for (int i = 0; i < 3; ++i) {
                int p = n0[i] + fc;
                float2 bb = *(const float2*)(sB2 + p);
                int r0w = mt * 16 + fr;
                float* ee = e[mt * 3 + i];
                float* yy = y[mt * 3 + i];
                float o0, o1, o2, o3;
                if (i < 2) {
                    // rotation pair: mu = col p, omega = col p+1
#pragma unroll
                    for (int hh = 0; hh < 2; ++hh) {
                        float mu = ee[2 * hh]     + bb.x;
                        float om = ee[2 * hh + 1] + bb.y;
                        float zm = DT * mu;
                        float ex = 1.f + zm + zm * zm * (0.5f + zm * (1.f / 6.f));
                        float zo = DT * om;
                        float zo2 = zo * zo;
                        float s = zo * (1.f - zo2 * (1.f / 6.f));
                        float c = 1.f - zo2 * (0.5f - zo2 * (1.f / 24.f));
                        float ye = yy[2 * hh], yo = yy[2 * hh + 1];
                        float ne = ex * (c * ye - s * yo);
                        float no = ex * (s * ye + c * yo);
                        yy[2 * hh] = ne; yy[2 * hh + 1] = no;
                    }
                } else {
                    // real part: y *= exp(DT*re), independent per column
#pragma unroll
                    for (int v = 0; v < 4; ++v) {
                        float re = ee[v] + ((v & 1) ? bb.y : bb.x);
                        float z = DT * re;
                        float ex = 1.f + z + z * z * (0.5f + z * (1.f / 6.f));
                        yy[v] *= ex;
                    }
                }
                o0 = yy[0]; o1 = yy[1]; o2 = yy[2]; o3 = yy[3];
                // store next A operand (bf16) + output (fp32)
                yAw[(r0w * WPAD1 + p) >> 1]       = pkbf(o0, o1);
                yAw[((r0w + 8) * WPAD1 + p) >> 1] = pkbf(o2, o3);
                float* orow = outBase + (size_t)(r0w) * (TSTEPS * KD) + (size_t)t * KD + p;
                *(float2*)(orow) = make_float2(o0, o1);
                *(float2*)(orow + (size_t)8 * TSTEPS * KD) = make_float2(o2, o3);
            }
        }
        __syncthreads();
    }
}

extern "C" void kernel_launch(void* const* d_in, const int* in_sizes, int n_in,
                              void* d_out, int out_size) {
    const float* x   = (const float*)d_in[0];
    const float* cW1 = (const float*)d_in[1];
    const float* cb1 = (const float*)d_in[2];
    const float* cW2 = (const float*)d_in[3];
    const float* cb2 = (const float*)d_in[4];
    const float* rW1 = (const float*)d_in[5];
    const float* rb1 = (const float*)d_in[6];
    const float* rW2 = (const float*)d_in[7];
    const float* rb2 = (const float*)d_in[8];
    float* out = (float*)d_out;

    cudaFuncSetAttribute(koopman_mma_kernel,
                         cudaFuncAttributeMaxDynamicSharedMemorySize, SMEM_BYTES);
    koopman_mma_kernel<<<CTAS, THREADS, SMEM_BYTES>>>(x, cW1, cb1, cW2, cb2,
                                                      rW1, rb1, rW2, rb2, out);
}

// round 11
// speedup vs baseline: 5.7220x; 1.1311x over previous
#include <cuda_runtime.h>
#include <cuda_bf16.h>

typedef unsigned int u32;
typedef unsigned long long u64;

#define THREADS 256
#define CTAS 128
#define ROWS 32
#define TSTEPS 64
#define KD 192
#define DT 0.01f

#define WPAD1 200   // halves per row for yA / h1 / WB1  (400 B = 16 mod 128 -> ldmatrix conflict-free)
#define WPAD2 136   // halves per row for WB2            (272 B = 16 mod 128)

// ---- smem byte offsets ----
#define SB_YA  0                          // [32][200] bf16 = 12800 B
#define SB_H1  12800                      // [32][200] bf16 = 12800 B
#define SB_WB1 25600                      // [192][200] bf16 = 76800 B (merged cW1 / rW1, n-major)
#define SB_WB2 102400                     // [192][136] bf16 = 52224 B (merged cW2 / rW2)
#define SB_B1  154624                     // [192] f32 merged bias1
#define SB_B2  155392                     // [192] f32 merged bias2
#define SMEM_BYTES 156160

__device__ __forceinline__ u32 smem_u32(const void* p) {
    u32 a;
    asm("{ .reg .u64 t; cvta.to.shared.u64 t, %1; cvt.u32.u64 %0, t; }" : "=r"(a) : "l"(p));
    return a;
}
__device__ __forceinline__ void ldsm4(u32* r, u32 addr) {
    asm volatile("ldmatrix.sync.aligned.m8n8.x4.shared.b16 {%0,%1,%2,%3}, [%4];"
                 : "=r"(r[0]), "=r"(r[1]), "=r"(r[2]), "=r"(r[3]) : "r"(addr));
}
__device__ __forceinline__ void ldsm2(u32* r, u32 addr) {
    asm volatile("ldmatrix.sync.aligned.m8n8.x2.shared.b16 {%0,%1}, [%2];"
                 : "=r"(r[0]), "=r"(r[1]) : "r"(addr));
}
__device__ __forceinline__ void mma16816(float* d, const u32* a, const u32* b) {
    asm volatile(
        "mma.sync.aligned.m16n8k16.row.col.f32.bf16.bf16.f32 "
        "{%0,%1,%2,%3}, {%4,%5,%6,%7}, {%8,%9}, {%0,%1,%2,%3};"
        : "+f"(d[0]), "+f"(d[1]), "+f"(d[2]), "+f"(d[3])
        : "r"(a[0]), "r"(a[1]), "r"(a[2]), "r"(a[3]), "r"(b[0]), "r"(b[1]));
}
__device__ __forceinline__ u32 pkbf(float a, float b) {
    __nv_bfloat162 h = __floats2bfloat162_rn(a, b);
    return *reinterpret_cast<u32*>(&h);
}
__device__ __forceinline__ float relu(float a) { return fmaxf(a, 0.f); }

__global__ __launch_bounds__(THREADS, 1)
void koopman_mma_kernel(const float* __restrict__ x,
                        const float* __restrict__ cW1, const float* __restrict__ cb1,
                        const float* __restrict__ cW2, const float* __restrict__ cb2,
                        const float* __restrict__ rW1, const float* __restrict__ rb1,
                        const float* __restrict__ rW2, const float* __restrict__ rb2,
                        float* __restrict__ out) {
    extern __shared__ char smem[];
    const u32 sbase = smem_u32(smem);
    const int tid = threadIdx.x;
    const int wid = tid >> 5;
    const int lane = tid & 31;

    __nv_bfloat16* WB1 = (__nv_bfloat16*)(smem + SB_WB1);
    __nv_bfloat16* WB2 = (__nv_bfloat16*)(smem + SB_WB2);
    float* sB1 = (float*)(smem + SB_B1);
    float* sB2 = (float*)(smem + SB_B2);
    u32* h1w = (u32*)(smem + SB_H1);
    u32* yAw = (u32*)(smem + SB_YA);

    // ---- pack merged weights (fp32 -> bf16) ----
    for (int i = tid; i < 192 * 192; i += THREADS) {
        int n = i / 192, k = i % 192;
        float v = (n < 128) ? cW1[n * 192 + k] : rW1[(n - 128) * 192 + k];
        WB1[n * WPAD1 + k] = __float2bfloat16(v);
    }
    for (int i = tid; i < 192 * 128; i += THREADS) {
        int n = i / 128, k = i % 128;
        if (n < 128)      WB2[n * WPAD2 + k] = __float2bfloat16(cW2[n * 128 + k]);
        else if (k < 64)  WB2[n * WPAD2 + k] = __float2bfloat16(rW2[(n - 128) * 64 + k]);
    }
    if (tid < 192) {
        sB1[tid] = (tid < 128) ? cb1[tid] : rb1[tid - 128];
        sB2[tid] = (tid < 128) ? cb2[tid] : rb2[tid - 128];
    }

    // ---- fragment geometry ----
    const int g = lane >> 3;
    const int rowA = ((g & 1) << 3) + (lane & 7);   // 0..15
    const int colA = (g >> 1) << 3;                 // 0 or 8
    const int rowB = lane & 7;
    const int colB = (g & 1) << 3;

    // warp n-tiles: w, w+8, w+16 -> cols 8w, 64+8w, 128+8w (2 complex + 1 real tile)
    int n0[3] = {8 * wid, 64 + 8 * wid, 128 + 8 * wid};

    const int rowBase = blockIdx.x * ROWS;
    const int fr = lane >> 2;                       // fragment row 0..7
    const int fc = 2 * (lane & 3);                  // fragment col offset (even)

    // ---- register y-state matching D-fragment layout ----
    float y[6][4];
#pragma unroll
    for (int mt = 0; mt < 2; ++mt)
#pragma unroll
        for (int i = 0; i < 3; ++i) {
            int p = n0[i] + fc;
            const float* xr = x + (size_t)(rowBase + mt * 16 + fr) * (TSTEPS * KD) + p;
            float2 v0 = *(const float2*)(xr);
            float2 v1 = *(const float2*)(xr + 8 * (TSTEPS * KD));
            y[mt * 3 + i][0] = v0.x; y[mt * 3 + i][1] = v0.y;
            y[mt * 3 + i][2] = v1.x; y[mt * 3 + i][3] = v1.y;
        }
    // initial yA (bf16 A operand)
#pragma unroll
    for (int mt = 0; mt < 2; ++mt)
#pragma unroll
        for (int i = 0; i < 3; ++i) {
            int p = n0[i] + fc;
            int r0w = mt * 16 + fr;
            yAw[(r0w * WPAD1 + p) >> 1]       = pkbf(y[mt * 3 + i][0], y[mt * 3 + i][1]);
            yAw[((r0w + 8) * WPAD1 + p) >> 1] = pkbf(y[mt * 3 + i][2], y[mt * 3 + i][3]);
        }
    __syncthreads();

    const u32 yAb  = sbase + SB_YA;
    const u32 h1b  = sbase + SB_H1;
    const u32 wb1b = sbase + SB_WB1;
    const u32 wb2b = sbase + SB_WB2;

    // ---- hoist ALL time-invariant B (weight) fragments into registers ----
    u32 b1[3][12][2];     // GEMM1: n-tile i, kt 0..11
#pragma unroll
    for (int i = 0; i < 3; ++i)
#pragma unroll
        for (int kt = 0; kt < 12; ++kt)
            ldsm2(b1[i][kt], wb1b + (u32)((n0[i] + rowB) * WPAD1 + kt * 16 + colB) * 2);
    u32 b2c[2][8][2];     // GEMM2 complex: n-tile i, kt 0..7
#pragma unroll
    for (int i = 0; i < 2; ++i)
#pragma unroll
        for (int kt = 0; kt < 8; ++kt)
            ldsm2(b2c[i][kt], wb2b + (u32)((n0[i] + rowB) * WPAD2 + kt * 16 + colB) * 2);
    u32 b2r[4][2];        // GEMM2 real: kt 0..3
#pragma unroll
    for (int kt = 0; kt < 4; ++kt)
        ldsm2(b2r[kt], wb2b + (u32)((n0[2] + rowB) * WPAD2 + kt * 16 + colB) * 2);

    float* outBase = out + (size_t)rowBase * TSTEPS * KD;

    for (int t = 0; t < TSTEPS; ++t) {
        // ===== GEMM1: [32,192] = yA[32,192] @ WB1^T, K=192 (B in registers) =====
        float d[6][4];
#pragma unroll
        for (int j = 0; j < 6; ++j) { d[j][0] = d[j][1] = d[j][2] = d[j][3] = 0.f; }
#pragma unroll
        for (int kt = 0; kt < 12; ++kt) {
            u32 a0[4], a1[4];
            ldsm4(a0, yAb + (u32)((rowA) * WPAD1 + kt * 16 + colA) * 2);
            ldsm4(a1, yAb + (u32)((16 + rowA) * WPAD1 + kt * 16 + colA) * 2);
#pragma unroll
            for (int i = 0; i < 3; ++i) {
                mma16816(d[i],     a0, b1[i][kt]);
                mma16816(d[3 + i], a1, b1[i][kt]);
            }
        }
        // epilogue 1: bias + relu -> h1 (bf16)
#pragma unroll
        for (int mt = 0; mt < 2; ++mt)
#pragma unroll
            for (int i = 0; i < 3; ++i) {
                int p = n0[i] + fc;
                float2 bb = *(const float2*)(sB1 + p);
                int r0w = mt * 16 + fr;
                float* dd = d[mt * 3 + i];
                h1w[(r0w * WPAD1 + p) >> 1]       = pkbf(relu(dd[0] + bb.x), relu(dd[1] + bb.y));
                h1w[((r0w + 8) * WPAD1 + p) >> 1] = pkbf(relu(dd[2] + bb.x), relu(dd[3] + bb.y));
            }
        __syncthreads();

        // ===== GEMM2: complex (K=128), real (K=64) — B in registers =====
        float e[6][4];
#pragma unroll
        for (int j = 0; j < 6; ++j) { e[j][0] = e[j][1] = e[j][2] = e[j][3] = 0.f; }
#pragma unroll
        for (int kt = 0; kt < 8; ++kt) {
            u32 a0[4], a1[4];
            ldsm4(a0, h1b + (u32)((rowA) * WPAD1 + kt * 16 + colA) * 2);
            ldsm4(a1, h1b + (u32)((16 + rowA) * WPAD1 + kt * 16 + colA) * 2);
#pragma unroll
            for (int i = 0; i < 2; ++i) {
                mma16816(e[i],     a0, b2c[i][kt]);
                mma16816(e[3 + i], a1, b2c[i][kt]);
            }
        }
#pragma unroll
        for (int kt = 0; kt < 4; ++kt) {
            u32 a0[4], a1[4];
            ldsm4(a0, h1b + (u32)((rowA) * WPAD1 + 128 + kt * 16 + colA) * 2);
            ldsm4(a1, h1b + (u32)((16 + rowA) * WPAD1 + 128 + kt * 16 + colA) * 2);
            mma16816(e[2], a0, b2r[kt]);
            mma16816(e[5], a1, b2r[kt]);
        }

        // ===== Phase C: Koopman update (polynomial exp/sin/cos), y fp32 in regs =====
#pragma unroll
        for (int mt = 0; mt < 2; ++mt) {
#pragma unroll
            for (int i = 0; i < 3; ++i) {
                int p = n0[i] + fc;
                float2 bb = *(const float2*)(sB2 + p);
                int r0w = mt * 16 + fr;
                float* ee = e[mt * 3 + i];
                float* yy = y[mt * 3 + i];
                if (i < 2) {
#pragma unroll
                    for (int hh = 0; hh < 2; ++hh) {
                        float mu = ee[2 * hh]     + bb.x;
                        float om = ee[2 * hh + 1] + bb.y;
                        float zm = DT * mu;
                        float ex = 1.f + zm + zm * zm * (0.5f + zm * (1.f / 6.f));
                        float zo = DT * om;
                        float zo2 = zo * zo;
                        float s = zo * (1.f - zo2 * (1.f / 6.f));
                        float c = 1.f - zo2 * (0.5f - zo2 * (1.f / 24.f));
                        float ye = yy[2 * hh], yo = yy[2 * hh + 1];
                        float ne = ex * (c * ye - s * yo);
                        float no = ex * (s * ye + c * yo);
                        yy[2 * hh] = ne; yy[2 * hh + 1] = no;
                    }
                } else {
#pragma unroll
                    for (int v = 0; v < 4; ++v) {
                        float re = ee[v] + ((v & 1) ? bb.y : bb.x);
                        float z = DT * re;
                        float ex = 1.f + z + z * z * (0.5f + z * (1.f / 6.f));
                        yy[v] *= ex;
                    }
                }
                // store next A operand (bf16) + output (fp32)
                yAw[(r0w * WPAD1 + p) >> 1]       = pkbf(yy[0], yy[1]);
                yAw[((r0w + 8) * WPAD1 + p) >> 1] = pkbf(yy[2], yy[3]);
                float* orow = outBase + (size_t)(r0w) * (TSTEPS * KD) + (size_t)t * KD + p;
                *(float2*)(orow) = make_float2(yy[0], yy[1]);
                *(float2*)(orow + (size_t)8 * TSTEPS * KD) = make_float2(yy[2], yy[3]);
            }
        }
        __syncthreads();
    }
}

extern "C" void kernel_launch(void* const* d_in, const int* in_sizes, int n_in,
                              void* d_out, int out_size) {
    const float* x   = (const float*)d_in[0];
    const float* cW1 = (const float*)d_in[1];
    const float* cb1 = (const float*)d_in[2];
    const float* cW2 = (const float*)d_in[3];
    const float* cb2 = (const float*)d_in[4];
    const float* rW1 = (const float*)d_in[5];
    const float* rb1 = (const float*)d_in[6];
    const float* rW2 = (const float*)d_in[7];
    const float* rb2 = (const float*)d_in[8];
    float* out = (float*)d_out;

    cudaFuncSetAttribute(koopman_mma_kernel,
                         cudaFuncAttributeMaxDynamicSharedMemorySize, SMEM_BYTES);
    koopman_mma_kernel<<<CTAS, THREADS, SMEM_BYTES>>>(x, cW1, cb1, cW2, cb2,
                                                      rW1, rb1, rW2, rb2, out);
}

// round 12
// speedup vs baseline: 5.9366x; 1.0375x over previous
#include <cuda_runtime.h>
#include <cuda_bf16.h>

typedef unsigned int u32;
typedef unsigned long long u64;

#define THREADS 512
#define CTAS 128
#define ROWS 32
#define TSTEPS 64
#define KD 192
#define DT 0.01f

#define WPAD1 200   // halves per row for yA / h1 / WB1  (400 B = 16 mod 128 -> ldmatrix conflict-free)
#define WPAD2 136   // halves per row for WB2            (272 B = 16 mod 128)

// ---- smem byte offsets ----
#define SB_YA  0                          // [32][200] bf16 = 12800 B
#define SB_H1  12800                      // [32][200] bf16 = 12800 B
#define SB_WB1 25600                      // [192][200] bf16 = 76800 B (merged cW1 / rW1, n-major)
#define SB_WB2 102400                     // [192][136] bf16 = 52224 B (merged cW2 / rW2)
#define SB_B1  154624                     // [192] f32 merged bias1
#define SB_B2  155392                     // [192] f32 merged bias2
#define SMEM_BYTES 156160

__device__ __forceinline__ u32 smem_u32(const void* p) {
    u32 a;
    asm("{ .reg .u64 t; cvta.to.shared.u64 t, %1; cvt.u32.u64 %0, t; }" : "=r"(a) : "l"(p));
    return a;
}
__device__ __forceinline__ void ldsm4(u32* r, u32 addr) {
    asm volatile("ldmatrix.sync.aligned.m8n8.x4.shared.b16 {%0,%1,%2,%3}, [%4];"
                 : "=r"(r[0]), "=r"(r[1]), "=r"(r[2]), "=r"(r[3]) : "r"(addr));
}
__device__ __forceinline__ void ldsm2(u32* r, u32 addr) {
    asm volatile("ldmatrix.sync.aligned.m8n8.x2.shared.b16 {%0,%1}, [%2];"
                 : "=r"(r[0]), "=r"(r[1]) : "r"(addr));
}
__device__ __forceinline__ void mma16816(float* d, const u32* a, const u32* b) {
    asm volatile(
        "mma.sync.aligned.m16n8k16.row.col.f32.bf16.bf16.f32 "
        "{%0,%1,%2,%3}, {%4,%5,%6,%7}, {%8,%9}, {%0,%1,%2,%3};"
        : "+f"(d[0]), "+f"(d[1]), "+f"(d[2]), "+f"(d[3])
        : "r"(a[0]), "r"(a[1]), "r"(a[2]), "r"(a[3]), "r"(b[0]), "r"(b[1]));
}
__device__ __forceinline__ u32 pkbf(float a, float b) {
    __nv_bfloat162 h = __floats2bfloat162_rn(a, b);
    return *reinterpret_cast<u32*>(&h);
}
__device__ __forceinline__ float relu(float a) { return fmaxf(a, 0.f); }

__global__ __launch_bounds__(THREADS, 1)
void koopman_mma_kernel(const float* __restrict__ x,
                        const float* __restrict__ cW1, const float* __restrict__ cb1,
                        const float* __restrict__ cW2, const float* __restrict__ cb2,
                        const float* __restrict__ rW1, const float* __restrict__ rb1,
                        const float* __restrict__ rW2, const float* __restrict__ rb2,
                        float* __restrict__ out) {
    extern __shared__ char smem[];
    const u32 sbase = smem_u32(smem);
    const int tid = threadIdx.x;
    const int wid = tid >> 5;
    const int lane = tid & 31;

    __nv_bfloat16* WB1 = (__nv_bfloat16*)(smem + SB_WB1);
    __nv_bfloat16* WB2 = (__nv_bfloat16*)(smem + SB_WB2);
    float* sB1 = (float*)(smem + SB_B1);
    float* sB2 = (float*)(smem + SB_B2);
    u32* h1w = (u32*)(smem + SB_H1);
    u32* yAw = (u32*)(smem + SB_YA);

    // ---- pack merged weights (fp32 -> bf16) ----
    for (int i = tid; i < 192 * 192; i += THREADS) {
        int n = i / 192, k = i % 192;
        float v = (n < 128) ? cW1[n * 192 + k] : rW1[(n - 128) * 192 + k];
        WB1[n * WPAD1 + k] = __float2bfloat16(v);
    }
    for (int i = tid; i < 192 * 128; i += THREADS) {
        int n = i / 128, k = i % 128;
        if (n < 128)      WB2[n * WPAD2 + k] = __float2bfloat16(cW2[n * 128 + k]);
        else if (k < 64)  WB2[n * WPAD2 + k] = __float2bfloat16(rW2[(n - 128) * 64 + k]);
    }
    if (tid < 192) {
        sB1[tid] = (tid < 128) ? cb1[tid] : rb1[tid - 128];
        sB2[tid] = (tid < 128) ? cb2[tid] : rb2[tid - 128];
    }

    // ---- warp work assignment: warp = (mt, q) ----
    const int q  = wid & 7;       // n-tile group 0..7
    const int mt = wid >> 3;      // m-tile 0..1 (rows mt*16 .. mt*16+15)

    // ---- fragment geometry ----
    const int g = lane >> 3;
    const int rowA = mt * 16 + ((g & 1) << 3) + (lane & 7);   // global row 0..31
    const int colA = (g >> 1) << 3;                            // 0 or 8
    const int rowB = lane & 7;
    const int colB = (g & 1) << 3;

    // warp n-tiles: q, q+8, q+16 -> cols 8q, 64+8q, 128+8q (2 complex + 1 real)
    int n0[3] = {8 * q, 64 + 8 * q, 128 + 8 * q};

    const int rowBase = blockIdx.x * ROWS;
    const int fr = lane >> 2;                       // fragment row 0..7
    const int fc = 2 * (lane & 3);                  // fragment col offset (even)
    const int r0w = mt * 16 + fr;                   // this thread's first output row

    // ---- register y-state matching D-fragment layout ----
    float y[3][4];
#pragma unroll
    for (int i = 0; i < 3; ++i) {
        int p = n0[i] + fc;
        const float* xr = x + (size_t)(rowBase + r0w) * (TSTEPS * KD) + p;
        float2 v0 = *(const float2*)(xr);
        float2 v1 = *(const float2*)(xr + 8 * (TSTEPS * KD));
        y[i][0] = v0.x; y[i][1] = v0.y;
        y[i][2] = v1.x; y[i][3] = v1.y;
    }
    // initial yA (bf16 A operand)
#pragma unroll
    for (int i = 0; i < 3; ++i) {
        int p = n0[i] + fc;
        yAw[(r0w * WPAD1 + p) >> 1]       = pkbf(y[i][0], y[i][1]);
        yAw[((r0w + 8) * WPAD1 + p) >> 1] = pkbf(y[i][2], y[i][3]);
    }
    __syncthreads();

    const u32 yAb  = sbase + SB_YA;
    const u32 h1b  = sbase + SB_H1;
    const u32 wb1b = sbase + SB_WB1;
    const u32 wb2b = sbase + SB_WB2;

    // ---- hoist GEMM1 B (weight) fragments into registers (72 regs) ----
    u32 b1[3][12][2];
#pragma unroll
    for (int i = 0; i < 3; ++i)
#pragma unroll
        for (int kt = 0; kt < 12; ++kt)
            ldsm2(b1[i][kt], wb1b + (u32)((n0[i] + rowB) * WPAD1 + kt * 16 + colB) * 2);

    float* outBase = out + (size_t)rowBase * TSTEPS * KD;

    for (int t = 0; t < TSTEPS; ++t) {
        // ===== GEMM1: rows [mt*16,mt*16+16) x cols n0[] , K=192 (B in registers) =====
        float d[3][4];
#pragma unroll
        for (int j = 0; j < 3; ++j) { d[j][0] = d[j][1] = d[j][2] = d[j][3] = 0.f; }
#pragma unroll
        for (int kt = 0; kt < 12; ++kt) {
            u32 a[4];
            ldsm4(a, yAb + (u32)(rowA * WPAD1 + kt * 16 + colA) * 2);
#pragma unroll
            for (int i = 0; i < 3; ++i)
                mma16816(d[i], a, b1[i][kt]);
        }
        // epilogue 1: bias + relu -> h1 (bf16)
#pragma unroll
        for (int i = 0; i < 3; ++i) {
            int p = n0[i] + fc;
            float2 bb = *(const float2*)(sB1 + p);
            h1w[(r0w * WPAD1 + p) >> 1]       = pkbf(relu(d[i][0] + bb.x), relu(d[i][1] + bb.y));
            h1w[((r0w + 8) * WPAD1 + p) >> 1] = pkbf(relu(d[i][2] + bb.x), relu(d[i][3] + bb.y));
        }
        __syncthreads();

        // ===== GEMM2: complex (K=128), real (K=64) — B from smem =====
        float e[3][4];
#pragma unroll
        for (int j = 0; j < 3; ++j) { e[j][0] = e[j][1] = e[j][2] = e[j][3] = 0.f; }
#pragma unroll
        for (int kt = 0; kt < 8; ++kt) {
            u32 a[4];
            ldsm4(a, h1b + (u32)(rowA * WPAD1 + kt * 16 + colA) * 2);
#pragma unroll
            for (int i = 0; i < 2; ++i) {
                u32 b[2];
                ldsm2(b, wb2b + (u32)((n0[i] + rowB) * WPAD2 + kt * 16 + colB) * 2);
                mma16816(e[i], a, b);
            }
        }
#pragma unroll
        for (int kt = 0; kt < 4; ++kt) {
            u32 a[4];
            ldsm4(a, h1b + (u32)(rowA * WPAD1 + 128 + kt * 16 + colA) * 2);
            u32 b[2];
            ldsm2(b, wb2b + (u32)((n0[2] + rowB) * WPAD2 + kt * 16 + colB) * 2);
            mma16816(e[2], a, b);
        }

        // ===== Phase C: Koopman update (polynomial exp/sin/cos), y fp32 in regs =====
#pragma unroll
        for (int i = 0; i < 3; ++i) {
            int p = n0[i] + fc;
            float2 bb = *(const float2*)(sB2 + p);
            float* ee = e[i];
            float* yy = y[i];
            if (i < 2) {
#pragma unroll
                for (int hh = 0; hh < 2; ++hh) {
                    float mu = ee[2 * hh]     + bb.x;
                    float om = ee[2 * hh + 1] + bb.y;
                    float zm = DT * mu;
                    float ex = 1.f + zm + zm * zm * (0.5f + zm * (1.f / 6.f));
                    float zo = DT * om;
                    float zo2 = zo * zo;
                    float s = zo * (1.f - zo2 * (1.f / 6.f));
                    float c = 1.f - zo2 * (0.5f - zo2 * (1.f / 24.f));
                    float ye = yy[2 * hh], yo = yy[2 * hh + 1];
                    float ne = ex * (c * ye - s * yo);
                    float no = ex * (s * ye + c * yo);
                    yy[2 * hh] = ne; yy[2 * hh + 1] = no;
                }
            } else {
#pragma unroll
                for (int v = 0; v < 4; ++v) {
                    float re = ee[v] + ((v & 1) ? bb.y : bb.x);
                    float z = DT * re;
                    float ex = 1.f + z + z * z * (0.5f + z * (1.f / 6.f));
                    yy[v] *= ex;
                }
            }
            // store next A operand (bf16) + output (fp32)
            yAw[(r0w * WPAD1 + p) >> 1]       = pkbf(yy[0], yy[1]);
            yAw[((r0w + 8) * WPAD1 + p) >> 1] = pkbf(yy[2], yy[3]);
            float* orow = outBase + (size_t)(r0w) * (TSTEPS * KD) + (size_t)t * KD + p;
            *(float2*)(orow) = make_float2(yy[0], yy[1]);
            *(float2*)(orow + (size_t)8 * TSTEPS * KD) = make_float2(yy[2], yy[3]);
        }
        __syncthreads();
    }
}

extern "C" void kernel_launch(void* const* d_in, const int* in_sizes, int n_in,
                              void* d_out, int out_size) {
    const float* x   = (const float*)d_in[0];
    const float* cW1 = (const float*)d_in[1];
    const float* cb1 = (const float*)d_in[2];
    const float* cW2 = (const float*)d_in[3];
    const float* cb2 = (const float*)d_in[4];
    const float* rW1 = (const float*)d_in[5];
    const float* rb1 = (const float*)d_in[6];
    const float* rW2 = (const float*)d_in[7];
    const float* rb2 = (const float*)d_in[8];
    float* out = (float*)d_out;

    cudaFuncSetAttribute(koopman_mma_kernel,
                         cudaFuncAttributeMaxDynamicSharedMemorySize, SMEM_BYTES);
    koopman_mma_kernel<<<CTAS, THREADS, SMEM_BYTES>>>(x, cW1, cb1, cW2, cb2,
                                                      rW1, rb1, rW2, rb2, out);
}